// round 16
// baseline (speedup 1.0000x reference)
#include <cuda_runtime.h>
#include <math.h>

#define PTS    4096
#define BATCH  32
#define NBX    32
#define NBY    32
#define NCF    (NBX * NBY)              // 1024 fine cells (~4 pts/cell)
#define TPB    512
#define TPB_B  1024
#define NKEYS  (2 * BATCH)              // 64 (b,dir) keys
#define WT_PER_KEY (PTS / 32)           // 128 warp-tickets (32 queries each)
#define NBLOCKS 444                     // 3 blocks/SM x 148 SMs: one full wave
#define SMEM_SCAN (PTS * 16)            // 64KB dynamic: staged targets

// Fine-serpentine-ordered points, two views:
//   g_fine : PAIR-PACKED  {-2x0,-2x1,-2y0,-2y1}{-2z0,-2z1,g2_0,g2_1}  (targets)
//   g_plain: plain float4 {-2x,-2y,-2z,|p|^2}                         (queries)
__device__ float4 g_fine [2 * BATCH * PTS];
__device__ float4 g_plain[2 * BATCH * PTS];
__device__ int    g_cdfF [2 * BATCH * (NCF + 1)];
__device__ float4 g_meta [2 * BATCH];    // {x0, invwx, y0, invwy}
__device__ int    g_qhead[NKEYS];        // per-key warp-ticket counters

// Serpentine cell id: y runs upward in even columns, downward in odd ones.
__device__ __forceinline__ int serp_cell(int cx, int cy) {
    int cys = (cx & 1) ? (NBY - 1 - cy) : cy;
    return cx * NBY + cys;
}

// ---- Blackwell packed f32x2 helpers ----------------------------------------
__device__ __forceinline__ unsigned long long splat2(float v) {
    unsigned long long r;
    asm("mov.b64 %0, {%1, %1};" : "=l"(r) : "f"(v));
    return r;
}
__device__ __forceinline__ unsigned long long fma2(unsigned long long a,
                                                   unsigned long long b,
                                                   unsigned long long c) {
    unsigned long long d;
    asm("fma.rn.f32x2 %0, %1, %2, %3;" : "=l"(d) : "l"(a), "l"(b), "l"(c));
    return d;
}
__device__ __forceinline__ void min2_acc(unsigned long long t, float& a0, float& a1) {
    float lo, hi;
    asm("mov.b64 {%0, %1}, %2;" : "=f"(lo), "=f"(hi) : "l"(t));
    a0 = fminf(a0, lo);
    a1 = fminf(a1, hi);
}

// ---------------------------------------------------------------------------
// Kernel 1: per (batch,set) serpentine 2-D counting sort. Grid (BATCH, 2).
// Also resets the per-key ticket counters and output scalar.
// ---------------------------------------------------------------------------
__global__ __launch_bounds__(TPB_B) void build_kernel(
    const float* __restrict__ pred, const float* __restrict__ gt,
    float* __restrict__ out)
{
    __shared__ unsigned hist[NCF];
    __shared__ unsigned offs[NCF];
    __shared__ unsigned wscan[32];
    __shared__ float    red[128];
    __shared__ float    sm[4];

    const int b = blockIdx.x, set = blockIdx.y, tid = threadIdx.x;
    const int lane = tid & 31, wid = tid >> 5;
    const unsigned FULL = 0xFFFFFFFFu;

    if (b == 0 && set == 0) {
        if (tid == 0) out[0] = 0.0f;
        if (tid < NKEYS) g_qhead[tid] = 0;
    }

    const float* __restrict__ src = (set ? gt : pred) + (size_t)b * PTS * 3;

    // ---- pass 1: bbox of (x, y) ----
    float mnx = 3e38f, mxx = -3e38f, mny = 3e38f, mxy = -3e38f;
    for (int i = tid; i < PTS; i += TPB_B) {
        float x = src[3 * i], y = src[3 * i + 1];
        mnx = fminf(mnx, x); mxx = fmaxf(mxx, x);
        mny = fminf(mny, y); mxy = fmaxf(mxy, y);
    }
    #pragma unroll
    for (int o = 16; o > 0; o >>= 1) {
        mnx = fminf(mnx, __shfl_xor_sync(FULL, mnx, o));
        mxx = fmaxf(mxx, __shfl_xor_sync(FULL, mxx, o));
        mny = fminf(mny, __shfl_xor_sync(FULL, mny, o));
        mxy = fmaxf(mxy, __shfl_xor_sync(FULL, mxy, o));
    }
    if (lane == 0) { red[wid] = mnx; red[32 + wid] = mxx; red[64 + wid] = mny; red[96 + wid] = mxy; }
    if (tid < NCF) hist[tid] = 0;
    __syncthreads();
    if (tid == 0) {
        float a = red[0], c = red[32], e = red[64], f = red[96];
        #pragma unroll
        for (int i = 1; i < 32; i++) {
            a = fminf(a, red[i]);      c = fmaxf(c, red[32 + i]);
            e = fminf(e, red[64 + i]); f = fmaxf(f, red[96 + i]);
        }
        sm[0] = a; sm[1] = (float)NBX / fmaxf(c - a, 1e-30f);
        sm[2] = e; sm[3] = (float)NBY / fmaxf(f - e, 1e-30f);
        g_meta[set * BATCH + b] = make_float4(sm[0], sm[1], sm[2], sm[3]);
    }
    __syncthreads();
    const float x0 = sm[0], invwx = sm[1], y0 = sm[2], invwy = sm[3];

    // ---- pass 2: histogram (serpentine cells) ----
    for (int i = tid; i < PTS; i += TPB_B) {
        float x = src[3 * i], y = src[3 * i + 1];
        int cx = (int)fminf(fmaxf((x - x0) * invwx, 0.0f), (float)(NBX - 1));
        int cy = (int)fminf(fmaxf((y - y0) * invwy, 0.0f), (float)(NBY - 1));
        atomicAdd(&hist[serp_cell(cx, cy)], 1u);
    }
    __syncthreads();

    // ---- exclusive scan over 1024 ----
    unsigned v = (tid < NCF) ? hist[tid] : 0u;
    unsigned inc = v;
    #pragma unroll
    for (int o = 1; o < 32; o <<= 1) {
        unsigned n = __shfl_up_sync(FULL, inc, o);
        if (lane >= o) inc += n;
    }
    if (lane == 31) wscan[wid] = inc;
    __syncthreads();
    if (wid == 0) {
        unsigned wv = wscan[lane];
        #pragma unroll
        for (int o = 1; o < 32; o <<= 1) {
            unsigned n = __shfl_up_sync(FULL, wv, o);
            if (lane >= o) wv += n;
        }
        wscan[lane] = wv;
    }
    __syncthreads();
    const int base = (set * BATCH + b) * (NCF + 1);
    if (tid < NCF) {
        unsigned excl = inc - v + (wid ? wscan[wid - 1] : 0u);
        offs[tid] = excl;
        g_cdfF[base + tid] = (int)excl;
        if (tid == 0) g_cdfF[base + NCF] = PTS;
    }
    __syncthreads();

    // ---- pass 3: scatter to pair-packed (targets) and plain (queries) ----
    float*  __restrict__ dstF = (float*)(g_fine + (size_t)(set * BATCH + b) * PTS);
    float4* __restrict__ dstP = g_plain + (size_t)(set * BATCH + b) * PTS;
    for (int i = tid; i < PTS; i += TPB_B) {
        float x = src[3 * i], y = src[3 * i + 1], z = src[3 * i + 2];
        int cx = (int)fminf(fmaxf((x - x0) * invwx, 0.0f), (float)(NBX - 1));
        int cy = (int)fminf(fmaxf((y - y0) * invwy, 0.0f), (float)(NBY - 1));
        float g2 = fmaf(x, x, fmaf(y, y, z * z));
        unsigned p = atomicAdd(&offs[serp_cell(cx, cy)], 1u);
        float* df = dstF + (size_t)(p >> 1) * 8 + (p & 1);
        df[0] = -2.0f * x; df[2] = -2.0f * y; df[4] = -2.0f * z; df[6] = g2;
        dstP[p] = make_float4(-2.0f * x, -2.0f * y, -2.0f * z, g2);
    }
}

// ---------------------------------------------------------------------------
// Kernel 2: ring-expansion NN scan; block staged once per key, warps steal
// 32-query tickets from the key's global counter. No block barrier in the
// work loop -> no warp coupling. Grid NBLOCKS x 512.
// ---------------------------------------------------------------------------
__global__ __launch_bounds__(TPB, 3) void chamfer_scan_kernel(float* __restrict__ out)
{
    extern __shared__ float4 st[];          // 4096 float4 = 2048 packed pairs
    __shared__ int   scdf[NCF + 1];
    __shared__ float wsum[TPB / 32];

    const int tid = threadIdx.x;
    const unsigned FULL = 0xFFFFFFFFu;
    const int lane = tid & 31;
    const int wid  = tid >> 5;

    // Block -> key (6-7 blocks per key, all keys covered, monotone).
    const int key = (int)(((long long)blockIdx.x * NKEYS) / gridDim.x);
    const int b   = key >> 1;
    const int dir = key & 1;
    const int qset = dir ? 0 : 1;
    const int tset = dir ? 1 : 0;

    // Stage this key's target set + cdf once.
    {
        const float4* tgt = g_fine + (size_t)(tset * BATCH + b) * PTS;
        const int*    cdf = g_cdfF + (tset * BATCH + b) * (NCF + 1);
        for (int i = tid; i < PTS; i += TPB) st[i] = __ldg(&tgt[i]);
        for (int i = tid; i < NCF + 1; i += TPB) scdf[i] = __ldg(&cdf[i]);
    }
    __syncthreads();

    const float4 m = __ldg(&g_meta[tset * BATCH + b]);
    const float x0 = m.x, invwx = m.y, y0 = m.z, invwy = m.w;
    const float wx = 1.0f / invwx, wy = 1.0f / invwy;
    const float4* qry = g_plain + (size_t)(qset * BATCH + b) * PTS;
    const ulonglong2* sp = (const ulonglong2*)st;

    float tsum = 0.0f;

    for (;;) {
        // Warp pulls a 32-query ticket.
        int w = 0;
        if (lane == 0) w = atomicAdd(&g_qhead[key], 1);
        w = __shfl_sync(FULL, w, 0);
        if (w >= WT_PER_KEY) break;

        const float4 qp = __ldg(&qry[w * 32 + lane]);
        const float px = -0.5f * qp.x, py = -0.5f * qp.y;
        const float p2 = qp.w;
        const unsigned long long sqx = splat2(qp.x * -0.5f),
                                 sqy = splat2(qp.y * -0.5f),
                                 sqz = splat2(qp.z * -0.5f);

        // Warp bbox of queries (tight thanks to serpentine ordering).
        float qxl = px, qxh = px, qyl = py, qyh = py;
        #pragma unroll
        for (int o = 16; o > 0; o >>= 1) {
            qxl = fminf(qxl, __shfl_xor_sync(FULL, qxl, o));
            qxh = fmaxf(qxh, __shfl_xor_sync(FULL, qxh, o));
            qyl = fminf(qyl, __shfl_xor_sync(FULL, qyl, o));
            qyh = fmaxf(qyh, __shfl_xor_sync(FULL, qyh, o));
        }

        float bt0 = 3e38f, bt1 = 3e38f, bt2 = 3e38f, bt3 = 3e38f;

        #define PAIR(JP, A0, A1) {                                             \
            ulonglong2 u0 = sp[2 * (JP)];                                      \
            ulonglong2 u1 = sp[2 * (JP) + 1];                                  \
            unsigned long long tt =                                            \
                fma2(sqz, u1.x, fma2(sqy, u0.y, fma2(sqx, u0.x, u1.y)));       \
            min2_acc(tt, A0, A1);                                              \
        }
        #define SCAN_RANGE(LO, HI) {                                           \
            int jp = (LO) >> 1, je = ((HI) + 1) >> 1;                          \
            for (; jp + 2 <= je; jp += 2) { PAIR(jp, bt0, bt1) PAIR(jp + 1, bt2, bt3) } \
            for (; jp < je; ++jp) PAIR(jp, bt0, bt1)                           \
        }
        #define SCAN_COL(BX, YA, YB) {                                         \
            int ya_ = (YA), yb_ = (YB);                                        \
            int a_  = ((BX) & 1) ? (NBY - 1 - yb_) : ya_;                      \
            int b2_ = ((BX) & 1) ? (NBY - 1 - ya_) : yb_;                      \
            int s_ = scdf[(BX) * NBY + a_];                                    \
            int e_ = scdf[(BX) * NBY + b2_ + 1];                               \
            SCAN_RANGE(s_, e_)                                                 \
        }

        // ---- Ring 0: warp bbox +- 1 cell ----
        int cXl = max((int)fminf(fmaxf((qxl - x0) * invwx, 0.0f), (float)(NBX - 1)) - 1, 0);
        int cXh = min((int)fminf(fmaxf((qxh - x0) * invwx, 0.0f), (float)(NBX - 1)) + 1, NBX - 1);
        int cYl = max((int)fminf(fmaxf((qyl - y0) * invwy, 0.0f), (float)(NBY - 1)) - 1, 0);
        int cYh = min((int)fminf(fmaxf((qyh - y0) * invwy, 0.0f), (float)(NBY - 1)) + 1, NBY - 1);
        for (int bx = cXl; bx <= cXh; ++bx) SCAN_COL(bx, cYl, cYh)

        // ---- Ring expansion (squared certification: no sqrt in loop) ----
        for (;;) {
            float bt = fminf(fminf(bt0, bt1), fminf(bt2, bt3));
            float d2best = fmaxf(bt + p2, 0.0f) * 1.00001f + 1e-5f;
            float db = 3e38f;
            if (cXl > 0)       db = fminf(db, px - (x0 + (float)cXl * wx));
            if (cXh < NBX - 1) db = fminf(db, (x0 + (float)(cXh + 1) * wx) - px);
            if (cYl > 0)       db = fminf(db, py - (y0 + (float)cYl * wy));
            if (cYh < NBY - 1) db = fminf(db, (y0 + (float)(cYh + 1) * wy) - py);
            if (__all_sync(FULL, d2best <= db * db)) break;

            int nXl = max(cXl - 1, 0), nXh = min(cXh + 1, NBX - 1);
            int nYl = max(cYl - 1, 0), nYh = min(cYh + 1, NBY - 1);
            if (nXl < cXl) SCAN_COL(nXl, nYl, nYh)
            if (nXh > cXh) SCAN_COL(nXh, nYl, nYh)
            for (int bx = cXl; bx <= cXh; ++bx) {
                if (nYl < cYl) SCAN_COL(bx, nYl, cYl - 1)
                if (nYh > cYh) SCAN_COL(bx, cYh + 1, nYh)
            }
            cXl = nXl; cXh = nXh; cYl = nYl; cYh = nYh;
        }
        #undef SCAN_COL
        #undef SCAN_RANGE
        #undef PAIR

        float bt = fminf(fminf(bt0, bt1), fminf(bt2, bt3));
        tsum += sqrtf(fmaxf(bt + p2, 1e-12f));
    }

    // ---- Block sum reduction + single atomic into out ----
    #pragma unroll
    for (int o = 16; o > 0; o >>= 1)
        tsum += __shfl_down_sync(FULL, tsum, o);

    if (lane == 0) wsum[wid] = tsum;
    __syncthreads();
    if (wid == 0) {
        float v = (lane < TPB / 32) ? wsum[lane] : 0.0f;
        #pragma unroll
        for (int o = 16; o > 0; o >>= 1)
            v += __shfl_down_sync(FULL, v, o);
        if (lane == 0)
            atomicAdd(out, v * (1.0f / (float)(BATCH * PTS)));
    }
}

extern "C" void kernel_launch(void* const* d_in, const int* in_sizes, int n_in,
                              void* d_out, int out_size)
{
    (void)in_sizes; (void)n_in; (void)out_size;
    const float* pred = (const float*)d_in[0];
    const float* gt   = (const float*)d_in[1];
    float* out        = (float*)d_out;

    cudaFuncSetAttribute(chamfer_scan_kernel,
                         cudaFuncAttributeMaxDynamicSharedMemorySize, SMEM_SCAN);

    dim3 bgrid(BATCH, 2);
    build_kernel<<<bgrid, TPB_B>>>(pred, gt, out);

    chamfer_scan_kernel<<<NBLOCKS, TPB, SMEM_SCAN>>>(out);
}

// round 17
// speedup vs baseline: 1.0349x; 1.0349x over previous
#include <cuda_runtime.h>
#include <math.h>

#define PTS    4096
#define BATCH  32
#define NBX    32
#define NBY    32
#define NCF    (NBX * NBY)              // 1024 fine cells (~4 pts/cell)
#define TPB    512
#define TPB_B  1024
#define NKEYS  (2 * BATCH)              // 64 (b,dir) keys
#define WT_PER_KEY (PTS / 32)           // 128 warp-tickets (32 queries each)
#define NBLOCKS 444                     // 3 blocks/SM x 148 SMs: one full wave
#define SMEM_SCAN (PTS * 16)            // 64KB dynamic: staged targets

// Fine-serpentine-ordered points, two views:
//   g_fine : PAIR-PACKED  {-2x0,-2x1,-2y0,-2y1}{-2z0,-2z1,g2_0,g2_1}  (targets)
//   g_plain: plain float4 {-2x,-2y,-2z,|p|^2}                         (queries)
__device__ float4 g_fine [2 * BATCH * PTS];
__device__ float4 g_plain[2 * BATCH * PTS];
__device__ int    g_cdfF [2 * BATCH * (NCF + 1)];
__device__ float4 g_meta [2 * BATCH];    // {x0, invwx, y0, invwy}
__device__ int    g_qhead[NKEYS];        // per-key warp-ticket counters

// Serpentine cell id: y runs upward in even columns, downward in odd ones.
__device__ __forceinline__ int serp_cell(int cx, int cy) {
    int cys = (cx & 1) ? (NBY - 1 - cy) : cy;
    return cx * NBY + cys;
}

// ---- Blackwell packed f32x2 helpers ----------------------------------------
__device__ __forceinline__ unsigned long long splat2(float v) {
    unsigned long long r;
    asm("mov.b64 %0, {%1, %1};" : "=l"(r) : "f"(v));
    return r;
}
__device__ __forceinline__ unsigned long long fma2(unsigned long long a,
                                                   unsigned long long b,
                                                   unsigned long long c) {
    unsigned long long d;
    asm("fma.rn.f32x2 %0, %1, %2, %3;" : "=l"(d) : "l"(a), "l"(b), "l"(c));
    return d;
}
__device__ __forceinline__ void min2_acc(unsigned long long t, float& a0, float& a1) {
    float lo, hi;
    asm("mov.b64 {%0, %1}, %2;" : "=f"(lo), "=f"(hi) : "l"(t));
    a0 = fminf(a0, lo);
    a1 = fminf(a1, hi);
}

// ---------------------------------------------------------------------------
// Kernel 1: per (batch,set) serpentine 2-D counting sort. Grid (BATCH, 2).
// Also resets the per-key ticket counters and output scalar.
// ---------------------------------------------------------------------------
__global__ __launch_bounds__(TPB_B) void build_kernel(
    const float* __restrict__ pred, const float* __restrict__ gt,
    float* __restrict__ out)
{
    __shared__ unsigned hist[NCF];
    __shared__ unsigned offs[NCF];
    __shared__ unsigned wscan[32];
    __shared__ float    red[128];
    __shared__ float    sm[4];

    const int b = blockIdx.x, set = blockIdx.y, tid = threadIdx.x;
    const int lane = tid & 31, wid = tid >> 5;
    const unsigned FULL = 0xFFFFFFFFu;

    if (b == 0 && set == 0) {
        if (tid == 0) out[0] = 0.0f;
        if (tid < NKEYS) g_qhead[tid] = 0;
    }

    const float* __restrict__ src = (set ? gt : pred) + (size_t)b * PTS * 3;

    // ---- pass 1: bbox of (x, y) ----
    float mnx = 3e38f, mxx = -3e38f, mny = 3e38f, mxy = -3e38f;
    for (int i = tid; i < PTS; i += TPB_B) {
        float x = src[3 * i], y = src[3 * i + 1];
        mnx = fminf(mnx, x); mxx = fmaxf(mxx, x);
        mny = fminf(mny, y); mxy = fmaxf(mxy, y);
    }
    #pragma unroll
    for (int o = 16; o > 0; o >>= 1) {
        mnx = fminf(mnx, __shfl_xor_sync(FULL, mnx, o));
        mxx = fmaxf(mxx, __shfl_xor_sync(FULL, mxx, o));
        mny = fminf(mny, __shfl_xor_sync(FULL, mny, o));
        mxy = fmaxf(mxy, __shfl_xor_sync(FULL, mxy, o));
    }
    if (lane == 0) { red[wid] = mnx; red[32 + wid] = mxx; red[64 + wid] = mny; red[96 + wid] = mxy; }
    if (tid < NCF) hist[tid] = 0;
    __syncthreads();
    if (tid == 0) {
        float a = red[0], c = red[32], e = red[64], f = red[96];
        #pragma unroll
        for (int i = 1; i < 32; i++) {
            a = fminf(a, red[i]);      c = fmaxf(c, red[32 + i]);
            e = fminf(e, red[64 + i]); f = fmaxf(f, red[96 + i]);
        }
        sm[0] = a; sm[1] = (float)NBX / fmaxf(c - a, 1e-30f);
        sm[2] = e; sm[3] = (float)NBY / fmaxf(f - e, 1e-30f);
        g_meta[set * BATCH + b] = make_float4(sm[0], sm[1], sm[2], sm[3]);
    }
    __syncthreads();
    const float x0 = sm[0], invwx = sm[1], y0 = sm[2], invwy = sm[3];

    // ---- pass 2: histogram (serpentine cells) ----
    for (int i = tid; i < PTS; i += TPB_B) {
        float x = src[3 * i], y = src[3 * i + 1];
        int cx = (int)fminf(fmaxf((x - x0) * invwx, 0.0f), (float)(NBX - 1));
        int cy = (int)fminf(fmaxf((y - y0) * invwy, 0.0f), (float)(NBY - 1));
        atomicAdd(&hist[serp_cell(cx, cy)], 1u);
    }
    __syncthreads();

    // ---- exclusive scan over 1024 ----
    unsigned v = (tid < NCF) ? hist[tid] : 0u;
    unsigned inc = v;
    #pragma unroll
    for (int o = 1; o < 32; o <<= 1) {
        unsigned n = __shfl_up_sync(FULL, inc, o);
        if (lane >= o) inc += n;
    }
    if (lane == 31) wscan[wid] = inc;
    __syncthreads();
    if (wid == 0) {
        unsigned wv = wscan[lane];
        #pragma unroll
        for (int o = 1; o < 32; o <<= 1) {
            unsigned n = __shfl_up_sync(FULL, wv, o);
            if (lane >= o) wv += n;
        }
        wscan[lane] = wv;
    }
    __syncthreads();
    const int base = (set * BATCH + b) * (NCF + 1);
    if (tid < NCF) {
        unsigned excl = inc - v + (wid ? wscan[wid - 1] : 0u);
        offs[tid] = excl;
        g_cdfF[base + tid] = (int)excl;
        if (tid == 0) g_cdfF[base + NCF] = PTS;
    }
    __syncthreads();

    // ---- pass 3: scatter to pair-packed (targets) and plain (queries) ----
    float*  __restrict__ dstF = (float*)(g_fine + (size_t)(set * BATCH + b) * PTS);
    float4* __restrict__ dstP = g_plain + (size_t)(set * BATCH + b) * PTS;
    for (int i = tid; i < PTS; i += TPB_B) {
        float x = src[3 * i], y = src[3 * i + 1], z = src[3 * i + 2];
        int cx = (int)fminf(fmaxf((x - x0) * invwx, 0.0f), (float)(NBX - 1));
        int cy = (int)fminf(fmaxf((y - y0) * invwy, 0.0f), (float)(NBY - 1));
        float g2 = fmaf(x, x, fmaf(y, y, z * z));
        unsigned p = atomicAdd(&offs[serp_cell(cx, cy)], 1u);
        float* df = dstF + (size_t)(p >> 1) * 8 + (p & 1);
        df[0] = -2.0f * x; df[2] = -2.0f * y; df[4] = -2.0f * z; df[6] = g2;
        dstP[p] = make_float4(-2.0f * x, -2.0f * y, -2.0f * z, g2);
    }
}

// ---------------------------------------------------------------------------
// Kernel 2: NN scan with ASYMMETRIC per-side window expansion.
// Block staged once per key; warps steal 32-query tickets. The scanned rect
// starts at the warp bbox and grows one strip at a time, only on sides some
// lane still needs (d2best > side_dist^2). Exact: loop exits only when every
// lane certifies against every side.
// ---------------------------------------------------------------------------
__global__ __launch_bounds__(TPB, 3) void chamfer_scan_kernel(float* __restrict__ out)
{
    extern __shared__ float4 st[];          // 4096 float4 = 2048 packed pairs
    __shared__ int   scdf[NCF + 1];
    __shared__ float wsum[TPB / 32];

    const int tid = threadIdx.x;
    const unsigned FULL = 0xFFFFFFFFu;
    const int lane = tid & 31;
    const int wid  = tid >> 5;

    // Block -> key (6-7 blocks per key, all keys covered, monotone).
    const int key = (int)(((long long)blockIdx.x * NKEYS) / gridDim.x);
    const int b   = key >> 1;
    const int dir = key & 1;
    const int qset = dir ? 0 : 1;
    const int tset = dir ? 1 : 0;

    // Stage this key's target set + cdf once.
    {
        const float4* tgt = g_fine + (size_t)(tset * BATCH + b) * PTS;
        const int*    cdf = g_cdfF + (tset * BATCH + b) * (NCF + 1);
        for (int i = tid; i < PTS; i += TPB) st[i] = __ldg(&tgt[i]);
        for (int i = tid; i < NCF + 1; i += TPB) scdf[i] = __ldg(&cdf[i]);
    }
    __syncthreads();

    const float4 m = __ldg(&g_meta[tset * BATCH + b]);
    const float x0 = m.x, invwx = m.y, y0 = m.z, invwy = m.w;
    const float wx = 1.0f / invwx, wy = 1.0f / invwy;
    const float4* qry = g_plain + (size_t)(qset * BATCH + b) * PTS;
    const ulonglong2* sp = (const ulonglong2*)st;

    float tsum = 0.0f;

    for (;;) {
        // Warp pulls a 32-query ticket.
        int w = 0;
        if (lane == 0) w = atomicAdd(&g_qhead[key], 1);
        w = __shfl_sync(FULL, w, 0);
        if (w >= WT_PER_KEY) break;

        const float4 qp = __ldg(&qry[w * 32 + lane]);
        const float px = -0.5f * qp.x, py = -0.5f * qp.y;
        const float p2 = qp.w;
        const unsigned long long sqx = splat2(qp.x * -0.5f),
                                 sqy = splat2(qp.y * -0.5f),
                                 sqz = splat2(qp.z * -0.5f);

        // Warp bbox of queries (tight thanks to serpentine ordering).
        float qxl = px, qxh = px, qyl = py, qyh = py;
        #pragma unroll
        for (int o = 16; o > 0; o >>= 1) {
            qxl = fminf(qxl, __shfl_xor_sync(FULL, qxl, o));
            qxh = fmaxf(qxh, __shfl_xor_sync(FULL, qxh, o));
            qyl = fminf(qyl, __shfl_xor_sync(FULL, qyl, o));
            qyh = fmaxf(qyh, __shfl_xor_sync(FULL, qyh, o));
        }

        float bt0 = 3e38f, bt1 = 3e38f, bt2 = 3e38f, bt3 = 3e38f;

        #define PAIR(JP, A0, A1) {                                             \
            ulonglong2 u0 = sp[2 * (JP)];                                      \
            ulonglong2 u1 = sp[2 * (JP) + 1];                                  \
            unsigned long long tt =                                            \
                fma2(sqz, u1.x, fma2(sqy, u0.y, fma2(sqx, u0.x, u1.y)));       \
            min2_acc(tt, A0, A1);                                              \
        }
        #define SCAN_RANGE(LO, HI) {                                           \
            int jp = (LO) >> 1, je = ((HI) + 1) >> 1;                          \
            for (; jp + 2 <= je; jp += 2) { PAIR(jp, bt0, bt1) PAIR(jp + 1, bt2, bt3) } \
            for (; jp < je; ++jp) PAIR(jp, bt0, bt1)                           \
        }
        #define SCAN_COL(BX, YA, YB) {                                         \
            int ya_ = (YA), yb_ = (YB);                                        \
            int a_  = ((BX) & 1) ? (NBY - 1 - yb_) : ya_;                      \
            int b2_ = ((BX) & 1) ? (NBY - 1 - ya_) : yb_;                      \
            int s_ = scdf[(BX) * NBY + a_];                                    \
            int e_ = scdf[(BX) * NBY + b2_ + 1];                               \
            SCAN_RANGE(s_, e_)                                                 \
        }

        // ---- Ring 0: bare warp bbox ----
        int cXl = (int)fminf(fmaxf((qxl - x0) * invwx, 0.0f), (float)(NBX - 1));
        int cXh = (int)fminf(fmaxf((qxh - x0) * invwx, 0.0f), (float)(NBX - 1));
        int cYl = (int)fminf(fmaxf((qyl - y0) * invwy, 0.0f), (float)(NBY - 1));
        int cYh = (int)fminf(fmaxf((qyh - y0) * invwy, 0.0f), (float)(NBY - 1));
        for (int bx = cXl; bx <= cXh; ++bx) SCAN_COL(bx, cYl, cYh)

        // ---- Asymmetric expansion: only sides some lane still needs ----
        for (;;) {
            float bt = fminf(fminf(bt0, bt1), fminf(bt2, bt3));
            float d2b = fmaxf(bt + p2, 0.0f) * 1.00001f + 1e-5f;

            float dxl = (cXl > 0)       ? px - (x0 + (float)cXl * wx)       : 3e38f;
            float dxh = (cXh < NBX - 1) ? (x0 + (float)(cXh + 1) * wx) - px : 3e38f;
            float dyl = (cYl > 0)       ? py - (y0 + (float)cYl * wy)       : 3e38f;
            float dyh = (cYh < NBY - 1) ? (y0 + (float)(cYh + 1) * wy) - py : 3e38f;

            unsigned want = 0;
            if (__ballot_sync(FULL, d2b > dxl * dxl)) want |= 1u;
            if (__ballot_sync(FULL, d2b > dxh * dxh)) want |= 2u;
            if (__ballot_sync(FULL, d2b > dyl * dyl)) want |= 4u;
            if (__ballot_sync(FULL, d2b > dyh * dyh)) want |= 8u;
            if (want == 0) break;

            int nXl = cXl, nXh = cXh;
            if (want & 1u) { nXl = cXl - 1; SCAN_COL(nXl, cYl, cYh) }
            if (want & 2u) { nXh = cXh + 1; SCAN_COL(nXh, cYl, cYh) }
            if (want & 4u) {
                int ny = cYl - 1;
                for (int bx = nXl; bx <= nXh; ++bx) SCAN_COL(bx, ny, ny)
                cYl = ny;
            }
            if (want & 8u) {
                int ny = cYh + 1;
                for (int bx = nXl; bx <= nXh; ++bx) SCAN_COL(bx, ny, ny)
                cYh = ny;
            }
            cXl = nXl; cXh = nXh;
        }
        #undef SCAN_COL
        #undef SCAN_RANGE
        #undef PAIR

        float bt = fminf(fminf(bt0, bt1), fminf(bt2, bt3));
        tsum += sqrtf(fmaxf(bt + p2, 1e-12f));
    }

    // ---- Block sum reduction + single atomic into out ----
    #pragma unroll
    for (int o = 16; o > 0; o >>= 1)
        tsum += __shfl_down_sync(FULL, tsum, o);

    if (lane == 0) wsum[wid] = tsum;
    __syncthreads();
    if (wid == 0) {
        float v = (lane < TPB / 32) ? wsum[lane] : 0.0f;
        #pragma unroll
        for (int o = 16; o > 0; o >>= 1)
            v += __shfl_down_sync(FULL, v, o);
        if (lane == 0)
            atomicAdd(out, v * (1.0f / (float)(BATCH * PTS)));
    }
}

extern "C" void kernel_launch(void* const* d_in, const int* in_sizes, int n_in,
                              void* d_out, int out_size)
{
    (void)in_sizes; (void)n_in; (void)out_size;
    const float* pred = (const float*)d_in[0];
    const float* gt   = (const float*)d_in[1];
    float* out        = (float*)d_out;

    cudaFuncSetAttribute(chamfer_scan_kernel,
                         cudaFuncAttributeMaxDynamicSharedMemorySize, SMEM_SCAN);

    dim3 bgrid(BATCH, 2);
    build_kernel<<<bgrid, TPB_B>>>(pred, gt, out);

    chamfer_scan_kernel<<<NBLOCKS, TPB, SMEM_SCAN>>>(out);
}